// round 8
// baseline (speedup 1.0000x reference)
#include <cuda_runtime.h>
#include <cuda_bf16.h>
#include <cstdint>

// OptionAttentionSum: out[b,o] = (sum_w sum_l [doc[b,l]==opt[b,o,w]] * prob[b,l]) / #nonzero words
//
// R6: split by OPTIONS (no cross-CTA reduction needed, unlike row-splitting).
// Grid = B*5 CTAs x 256 threads; each CTA owns (batch, 2 options) = 10 option
// words, streams the FULL doc row (4 int4 + 4 float4 per thread, MLP 8), probes
// a tiny 256-slot hash table (load 0.04 -> first probe empty ~96%, branchless),
// and writes its 2 outputs directly. Row re-read 5x but the 4MB working set
// lives in L2 (126MB) -> DRAM traffic unchanged. Small CTAs (2KB smem, ~40 regs)
// give 4-5 resident CTAs/SM so barrier/load stalls overlap across CTAs --
// fixing R5's 1-mega-CTA-per-SM serialization (occ 44%, issue 18%).

static constexpr int B = 128;
static constexpr int L = 4096;
static constexpr int O = 10;
static constexpr int W = 5;
static constexpr int OW = O * W;              // 50
static constexpr int SPLIT = 5;               // CTAs per batch row
static constexpr int OPT_PER_CTA = O / SPLIT; // 2 options per CTA
static constexpr int THREADS = 256;
static constexpr int VPT = L / 4 / THREADS;   // 4 int4 vectors per thread
static constexpr int TSIZE = 256;             // hash slots (power of 2), load 0.04
static constexpr int KEMPTY = (int)0x80000000;// impossible key (values in [0, 50000))

__device__ __forceinline__ unsigned hash_key(int key) {
    return ((unsigned)key * 2654435761u) >> (32 - 8);   // top 8 bits -> [0,256)
}

__global__ __launch_bounds__(THREADS)
void oas_kernel(const int* __restrict__ doc_idx,
                const float* __restrict__ doc_prob,
                const int* __restrict__ options,
                float* __restrict__ out) {
    __shared__ int   s_key[TSIZE];
    __shared__ float s_acc[TSIZE];

    const int bx  = blockIdx.x;
    const int b   = bx / SPLIT;       // batch row
    const int og  = bx - b * SPLIT;   // option group: options [2*og, 2*og+1]
    const int tid = threadIdx.x;

    // ---- issue ALL doc loads first: 8 independent 16B LDGs, latency hides behind setup ----
    const int4*   di4 = reinterpret_cast<const int4*>(doc_idx  + b * L);
    const float4* dp4 = reinterpret_cast<const float4*>(doc_prob + b * L);

    int4   d4[VPT];
    float4 p4[VPT];
    #pragma unroll
    for (int v = 0; v < VPT; v++) d4[v] = di4[tid + v * THREADS];
    #pragma unroll
    for (int v = 0; v < VPT; v++) p4[v] = dp4[tid + v * THREADS];

    // ---- init table: 1 slot per thread ----
    s_key[tid] = KEMPTY;
    s_acc[tid] = 0.0f;
    __syncthreads();

    // ---- insert this CTA's 10 option words ----
    const int* opt = options + b * OW + og * OPT_PER_CTA * W;
    if (tid < OPT_PER_CTA * W) {
        const int key = opt[tid];
        unsigned h = hash_key(key);
        while (true) {
            int old = atomicCAS(&s_key[h], KEMPTY, key);
            if (old == KEMPTY || old == key) break;
            h = (h + 1) & (TSIZE - 1);
        }
    }
    __syncthreads();

    // ---- probe the full row: 16 doc words per thread ----
    #pragma unroll
    for (int v = 0; v < VPT; v++) {
        const int   dk[4] = {d4[v].x, d4[v].y, d4[v].z, d4[v].w};
        const float pp[4] = {p4[v].x, p4[v].y, p4[v].z, p4[v].w};

        unsigned hh[4];
        int      k0[4];
        #pragma unroll
        for (int j = 0; j < 4; j++) hh[j] = hash_key(dk[j]);
        #pragma unroll
        for (int j = 0; j < 4; j++) k0[j] = s_key[hh[j]];   // 4 independent LDS

        #pragma unroll
        for (int j = 0; j < 4; j++) {
            if (k0[j] == dk[j]) {
                atomicAdd(&s_acc[hh[j]], pp[j]);            // hit (rare: ~0.8/row/CTA... per key set)
            } else if (k0[j] != KEMPTY) {                   // collided slot: walk cluster
                unsigned h = (hh[j] + 1) & (TSIZE - 1);
                while (true) {
                    const int k = s_key[h];
                    if (k == KEMPTY) break;
                    if (k == dk[j]) { atomicAdd(&s_acc[h], pp[j]); break; }
                    h = (h + 1) & (TSIZE - 1);
                }
            }
            // first slot EMPTY (~96%): miss, fall through
        }
    }
    __syncthreads();

    // ---- epilogue: 2 threads, one option each; plain stores ----
    if (tid < OPT_PER_CTA) {
        float sum = 0.0f;
        float cnt = 0.0f;
        #pragma unroll
        for (int w = 0; w < W; w++) {
            const int key = opt[tid * W + w];
            unsigned h = hash_key(key);
            while (s_key[h] != key) h = (h + 1) & (TSIZE - 1);  // guaranteed present
            sum += s_acc[h];
            if (key != 0) cnt += 1.0f;
        }
        out[b * O + og * OPT_PER_CTA + tid] = sum / cnt;
    }
}

extern "C" void kernel_launch(void* const* d_in, const int* in_sizes, int n_in,
                              void* d_out, int out_size) {
    const int*   doc_idx  = (const int*)d_in[0];     // (B, L) int32 (JAX-downgraded int64)
    const float* doc_prob = (const float*)d_in[1];   // (B, L) float32
    const int*   options  = (const int*)d_in[2];     // (B, O, W) int32
    float*       out      = (float*)d_out;           // (B, O) float32

    oas_kernel<<<B * SPLIT, THREADS>>>(doc_idx, doc_prob, options, out);
}

// round 10
// speedup vs baseline: 1.0504x; 1.0504x over previous
#include <cuda_runtime.h>
#include <cuda_bf16.h>
#include <cstdint>

// OptionAttentionSum: out[b,o] = (sum_w sum_l [doc[b,l]==opt[b,o,w]] * prob[b,l]) / #nonzero words
//
// R7: option-split with SPLIT=2 (sweet spot between R5 and R6).
//   R5 (grid 128x1024, 1x work): 6.27us kernel, issue 17.6% -> latency-bound, 20 idle SMs.
//   R6 (grid 640x256,  5x work): 8.22us kernel, issue 41.9% -> work-bound (5x probes).
// Here: grid 256 CTAs x 512 threads. Each CTA owns (batch, 5 options) = 25 keys,
// streams the full row (2 int4 + 2 float4 per thread, MLP 4), probes a 512-slot
// table (load 0.05 -> first probe ~95% EMPTY, branchless), writes 5 outputs
// directly. 2x probe work (cheap: R5 L1 was 6.3%), all SMs covered, ~1.7 CTAs/SM
// so stalls overlap across CTAs. No cross-CTA sync (R4 showed that costs +6us).

static constexpr int B = 128;
static constexpr int L = 4096;
static constexpr int O = 10;
static constexpr int W = 5;
static constexpr int OW = O * W;              // 50
static constexpr int SPLIT = 2;               // CTAs per batch row
static constexpr int OPT_PER_CTA = O / SPLIT; // 5 options per CTA
static constexpr int NKEYS = OPT_PER_CTA * W; // 25 keys per CTA
static constexpr int THREADS = 512;
static constexpr int VPT = L / 4 / THREADS;   // 2 int4 vectors per thread
static constexpr int TSIZE = 512;             // hash slots (power of 2), load ~0.05
static constexpr int KEMPTY = (int)0x80000000;// impossible key (values in [0, 50000))

__device__ __forceinline__ unsigned hash_key(int key) {
    return ((unsigned)key * 2654435761u) >> (32 - 9);   // top 9 bits -> [0,512)
}

__global__ __launch_bounds__(THREADS)
void oas_kernel(const int* __restrict__ doc_idx,
                const float* __restrict__ doc_prob,
                const int* __restrict__ options,
                float* __restrict__ out) {
    __shared__ int   s_key[TSIZE];
    __shared__ float s_acc[TSIZE];

    const int bx  = blockIdx.x;
    const int b   = bx >> 1;          // batch row
    const int og  = bx & 1;           // option group: options [5*og, 5*og+4]
    const int tid = threadIdx.x;

    // ---- issue all doc loads first: 4 independent 16B LDGs/thread ----
    const int4*   di4 = reinterpret_cast<const int4*>(doc_idx  + b * L);
    const float4* dp4 = reinterpret_cast<const float4*>(doc_prob + b * L);

    int4   d4[VPT];
    float4 p4[VPT];
    #pragma unroll
    for (int v = 0; v < VPT; v++) d4[v] = di4[tid + v * THREADS];
    #pragma unroll
    for (int v = 0; v < VPT; v++) p4[v] = dp4[tid + v * THREADS];

    // ---- init table: 1 slot per thread ----
    s_key[tid] = KEMPTY;
    s_acc[tid] = 0.0f;
    __syncthreads();

    // ---- insert this CTA's 25 option words ----
    const int* opt = options + b * OW + og * NKEYS;
    if (tid < NKEYS) {
        const int key = opt[tid];
        unsigned h = hash_key(key);
        while (true) {
            int old = atomicCAS(&s_key[h], KEMPTY, key);
            if (old == KEMPTY || old == key) break;
            h = (h + 1) & (TSIZE - 1);
        }
    }
    __syncthreads();

    // ---- probe the full row: 8 doc words per thread ----
    #pragma unroll
    for (int v = 0; v < VPT; v++) {
        const int   dk[4] = {d4[v].x, d4[v].y, d4[v].z, d4[v].w};
        const float pp[4] = {p4[v].x, p4[v].y, p4[v].z, p4[v].w};

        unsigned hh[4];
        int      k0[4];
        #pragma unroll
        for (int j = 0; j < 4; j++) hh[j] = hash_key(dk[j]);
        #pragma unroll
        for (int j = 0; j < 4; j++) k0[j] = s_key[hh[j]];   // 4 independent LDS

        #pragma unroll
        for (int j = 0; j < 4; j++) {
            if (k0[j] == dk[j]) {
                atomicAdd(&s_acc[hh[j]], pp[j]);            // first-probe hit
            } else if (k0[j] != KEMPTY) {                   // collided slot: walk cluster
                unsigned h = (hh[j] + 1) & (TSIZE - 1);
                while (true) {
                    const int k = s_key[h];
                    if (k == KEMPTY) break;
                    if (k == dk[j]) { atomicAdd(&s_acc[h], pp[j]); break; }
                    h = (h + 1) & (TSIZE - 1);
                }
            }
            // first slot EMPTY (~95%): miss, fall through
        }
    }
    __syncthreads();

    // ---- epilogue: 5 threads, one option each; plain stores ----
    if (tid < OPT_PER_CTA) {
        float sum = 0.0f;
        float cnt = 0.0f;
        #pragma unroll
        for (int w = 0; w < W; w++) {
            const int key = opt[tid * W + w];
            unsigned h = hash_key(key);
            while (s_key[h] != key) h = (h + 1) & (TSIZE - 1);  // guaranteed present
            sum += s_acc[h];
            if (key != 0) cnt += 1.0f;
        }
        out[b * O + og * OPT_PER_CTA + tid] = sum / cnt;
    }
}

extern "C" void kernel_launch(void* const* d_in, const int* in_sizes, int n_in,
                              void* d_out, int out_size) {
    const int*   doc_idx  = (const int*)d_in[0];     // (B, L) int32 (JAX-downgraded int64)
    const float* doc_prob = (const float*)d_in[1];   // (B, L) float32
    const int*   options  = (const int*)d_in[2];     // (B, O, W) int32
    float*       out      = (float*)d_out;           // (B, O) float32

    oas_kernel<<<B * SPLIT, THREADS>>>(doc_idx, doc_prob, options, out);
}

// round 12
// speedup vs baseline: 1.3029x; 1.2404x over previous
#include <cuda_runtime.h>
#include <cuda_bf16.h>
#include <cstdint>

// OptionAttentionSum: out[b,o] = (sum_w sum_l [doc[b,l]==opt[b,o,w]] * prob[b,l]) / #nonzero words
//
// R8 = R5 (best: 128 CTAs x 1024 thr, 2048-slot table) + critical-path cuts:
//  - options prefetched at kernel entry (overlaps table init; R5 serialized this
//    ~600-cycle DRAM load behind the first barrier)
//  - option keys cached in smem so the epilogue does LDS not LDG
//  - accumulator slots zeroed by the inserting threads (init phase touches s_key only)
// All-config evidence: kernel times cluster 6.3-8.2us vs a ~4.9us trivial-kernel
// floor (cold DVFS + replay ramp) -> only the serialized latency matters now.

static constexpr int B = 128;
static constexpr int L = 4096;
static constexpr int O = 10;
static constexpr int W = 5;
static constexpr int OW = O * W;          // 50
static constexpr int THREADS = 1024;      // L/4 -> one int4 per thread
static constexpr int TSIZE = 2048;        // hash slots (power of 2), load ~0.024
static constexpr int KEMPTY = (int)0x80000000;  // impossible key (values in [0, 50000))

__device__ __forceinline__ unsigned hash_key(int key) {
    return ((unsigned)key * 2654435761u) >> (32 - 11);   // top 11 bits -> [0,2048)
}

__global__ __launch_bounds__(THREADS, 1)
void oas_kernel(const int* __restrict__ doc_idx,
                const float* __restrict__ doc_prob,
                const int* __restrict__ options,
                float* __restrict__ out) {
    __shared__ int   s_key[TSIZE];
    __shared__ float s_acc[TSIZE];
    __shared__ int   s_opt[OW];

    const int b   = blockIdx.x;
    const int tid = threadIdx.x;

    // ---- issue ALL global loads first: doc (2x LDG.128) + options (tid<50) ----
    const int4   d4 = reinterpret_cast<const int4*>(doc_idx  + b * L)[tid];
    const float4 p4 = reinterpret_cast<const float4*>(doc_prob + b * L)[tid];

    int my_key = 0;
    if (tid < OW) my_key = options[b * OW + tid];   // latency overlaps init below

    // ---- init keys only (accs zeroed by inserters) ----
    s_key[tid]           = KEMPTY;
    s_key[tid + THREADS] = KEMPTY;
    __syncthreads();

    // ---- insert the (<=50) option words; cache keys in smem for the epilogue ----
    if (tid < OW) {
        s_opt[tid] = my_key;
        unsigned h = hash_key(my_key);
        while (true) {
            int old = atomicCAS(&s_key[h], KEMPTY, my_key);
            if (old == KEMPTY || old == my_key) break;
            h = (h + 1) & (TSIZE - 1);
        }
        s_acc[h] = 0.0f;   // zero the slot this key landed in (dups: same slot, same 0)
    }
    __syncthreads();

    // ---- probe: 4 independent first-probe LDS before any branching ----
    const int   dk[4] = {d4.x, d4.y, d4.z, d4.w};
    const float pp[4] = {p4.x, p4.y, p4.z, p4.w};

    unsigned hh[4];
    int      k0[4];
    #pragma unroll
    for (int j = 0; j < 4; j++) hh[j] = hash_key(dk[j]);
    #pragma unroll
    for (int j = 0; j < 4; j++) k0[j] = s_key[hh[j]];

    #pragma unroll
    for (int j = 0; j < 4; j++) {
        if (k0[j] == dk[j]) {
            atomicAdd(&s_acc[hh[j]], pp[j]);      // hit on first probe
        } else if (k0[j] != KEMPTY) {             // rare: collided slot, walk the cluster
            unsigned h = (hh[j] + 1) & (TSIZE - 1);
            while (true) {
                const int k = s_key[h];
                if (k == KEMPTY) break;
                if (k == dk[j]) { atomicAdd(&s_acc[h], pp[j]); break; }
                h = (h + 1) & (TSIZE - 1);
            }
        }
        // first slot EMPTY (~96%): miss, fall through
    }
    __syncthreads();

    // ---- epilogue: 10 threads, one option each; smem-only reads, plain stores ----
    if (tid < O) {
        float sum = 0.0f;
        float cnt = 0.0f;
        #pragma unroll
        for (int w = 0; w < W; w++) {
            const int key = s_opt[tid * W + w];
            unsigned h = hash_key(key);
            while (s_key[h] != key) h = (h + 1) & (TSIZE - 1);  // guaranteed present
            sum += s_acc[h];
            if (key != 0) cnt += 1.0f;
        }
        out[b * O + tid] = sum / cnt;
    }
}

extern "C" void kernel_launch(void* const* d_in, const int* in_sizes, int n_in,
                              void* d_out, int out_size) {
    const int*   doc_idx  = (const int*)d_in[0];     // (B, L) int32 (JAX-downgraded int64)
    const float* doc_prob = (const float*)d_in[1];   // (B, L) float32
    const int*   options  = (const int*)d_in[2];     // (B, O, W) int32
    float*       out      = (float*)d_out;           // (B, O) float32

    oas_kernel<<<B, THREADS>>>(doc_idx, doc_prob, options, out);
}